// round 1
// baseline (speedup 1.0000x reference)
#include <cuda_runtime.h>

#define NN 100000
#define EE 3200000
#define FF 128
#define NB4 32          // float4 per node row
#define ITERS 50
#define C1 0.5f         // ALPHA/(1+ALPHA)
#define C2 0.5f         // 1/(1+ALPHA)

// ---------------- device-global scratch (no allocations allowed) ----------------
__device__ __align__(16) float g_buf0[(size_t)NN * FF];
__device__ __align__(16) float g_buf1[(size_t)NN * FF];
__device__ __align__(16) float g_xc  [(size_t)NN * FF];
__device__ int   g_deg[NN];
__device__ float g_invdeg[NN];
__device__ int   g_rowptr[NN + 1];
__device__ int   g_cursor[NN];
__device__ int   g_col[EE];
__device__ float g_colsum[FF];
__device__ int   g_partials[128];
__device__ int   g_flag64;

// ---------------- dtype detection: int64 vs int32 edge_index ----------------
// If edge_index is int64 (little-endian), the high 32-bit word of every value is 0
// (values < 1e5). If int32, odd words are random edge values (P(all zero) ~ 0).
__global__ void k_detect(const int* __restrict__ ei32) {
    int t = threadIdx.x;                 // 32 threads
    int w = ei32[2 * t + 1];
    unsigned bal = __ballot_sync(0xffffffffu, w != 0);
    if (t == 0) g_flag64 = (bal == 0u) ? 1 : 0;
}

__global__ void k_zero() {
    int i = blockIdx.x * blockDim.x + threadIdx.x;
    if (i < NN) g_deg[i] = 0;
    if (i < FF) g_colsum[i] = 0.0f;
}

// ---------------- column sums for centering ----------------
#define ROWS_PER_BLK 256
__global__ void k_colsum(const float* __restrict__ x) {
    int c  = threadIdx.x;                // 128 threads = 128 feature cols
    int r0 = blockIdx.x * ROWS_PER_BLK;
    int r1 = r0 + ROWS_PER_BLK; if (r1 > NN) r1 = NN;
    float s = 0.0f;
    for (int r = r0; r < r1; r++) s += x[(size_t)r * FF + c];
    atomicAdd(&g_colsum[c], s);
}

// ---------------- degree count ----------------
__global__ void k_degree(const void* __restrict__ ei) {
    int e = blockIdx.x * blockDim.x + threadIdx.x;
    if (e >= EE) return;
    int r;
    if (g_flag64) r = (int)((const long long*)ei)[e];
    else          r = ((const int*)ei)[e];
    atomicAdd(&g_deg[r], 1);
}

// ---------------- exclusive scan of degrees -> rowptr ----------------
__global__ void k_scan1() {
    __shared__ int s[1024];
    int i = blockIdx.x * 1024 + threadIdx.x;
    int v = (i < NN) ? g_deg[i] : 0;
    s[threadIdx.x] = v;
    __syncthreads();
    for (int off = 1; off < 1024; off <<= 1) {
        int t = (threadIdx.x >= off) ? s[threadIdx.x - off] : 0;
        __syncthreads();
        s[threadIdx.x] += t;
        __syncthreads();
    }
    if (i < NN) g_rowptr[i] = s[threadIdx.x] - v;     // exclusive, pre-offset
    if (threadIdx.x == 1023) g_partials[blockIdx.x] = s[1023];
}

__global__ void k_scan2() {
    if (threadIdx.x == 0) {
        int run = 0;
        for (int b = 0; b < 98; b++) { int t = g_partials[b]; g_partials[b] = run; run += t; }
        g_rowptr[NN] = run;   // == EE
    }
}

__global__ void k_scan3() {
    int i = blockIdx.x * blockDim.x + threadIdx.x;
    if (i >= NN) return;
    int rp = g_rowptr[i] + g_partials[i >> 10];
    g_rowptr[i] = rp;
    g_cursor[i] = rp;
    g_invdeg[i] = 1.0f / (float)(g_deg[i] + 1);       // +1 self loop
}

// ---------------- scatter edges into CSR ----------------
__global__ void k_scatter(const void* __restrict__ ei) {
    int e = blockIdx.x * blockDim.x + threadIdx.x;
    if (e >= EE) return;
    int r, c;
    if (g_flag64) {
        const long long* p = (const long long*)ei;
        r = (int)p[e]; c = (int)p[(size_t)EE + e];
    } else {
        const int* p = (const int*)ei;
        r = p[e]; c = p[(size_t)EE + e];
    }
    int pos = atomicAdd(&g_cursor[r], 1);
    g_col[pos] = c;
}

// ---------------- center x -> xc, init cur=xc ----------------
__global__ void k_center(const float* __restrict__ x) {
    int i = blockIdx.x * blockDim.x + threadIdx.x;
    if (i >= NN * FF) return;
    float m = g_colsum[i & (FF - 1)] * (1.0f / (float)NN);
    float v = x[i] - m;
    g_xc[i]   = v;
    g_buf0[i] = v;
}

// ---------------- pull-based propagate: warp per node, float4 per lane ----------------
__global__ void __launch_bounds__(256) k_prop(int flip) {
    const float4* __restrict__ cur = (const float4*)(flip ? g_buf1 : g_buf0);
    float4*       __restrict__ out = (float4*)(flip ? g_buf0 : g_buf1);
    int gt   = blockIdx.x * blockDim.x + threadIdx.x;
    int node = gt >> 5;
    int lane = gt & 31;
    if (node >= NN) return;

    // self loop
    float4 acc = __ldg(&cur[(size_t)node * NB4 + lane]);

    int k   = g_rowptr[node];
    int end = g_rowptr[node + 1];
    for (; k + 4 <= end; k += 4) {
        int j0 = __ldg(&g_col[k]);
        int j1 = __ldg(&g_col[k + 1]);
        int j2 = __ldg(&g_col[k + 2]);
        int j3 = __ldg(&g_col[k + 3]);
        float4 a = __ldg(&cur[(size_t)j0 * NB4 + lane]);
        float4 b = __ldg(&cur[(size_t)j1 * NB4 + lane]);
        float4 c = __ldg(&cur[(size_t)j2 * NB4 + lane]);
        float4 d = __ldg(&cur[(size_t)j3 * NB4 + lane]);
        acc.x += a.x + b.x + c.x + d.x;
        acc.y += a.y + b.y + c.y + d.y;
        acc.z += a.z + b.z + c.z + d.z;
        acc.w += a.w + b.w + c.w + d.w;
    }
    for (; k < end; k++) {
        int j = __ldg(&g_col[k]);
        float4 a = __ldg(&cur[(size_t)j * NB4 + lane]);
        acc.x += a.x; acc.y += a.y; acc.z += a.z; acc.w += a.w;
    }

    float s = C1 * g_invdeg[node];
    float4 xcv = __ldg(&((const float4*)g_xc)[(size_t)node * NB4 + lane]);
    float4 o;
    o.x = s * acc.x + C2 * xcv.x;
    o.y = s * acc.y + C2 * xcv.y;
    o.z = s * acc.z + C2 * xcv.z;
    o.w = s * acc.w + C2 * xcv.w;
    out[(size_t)node * NB4 + lane] = o;
}

// ---------------- final GEMM: out = buf0 @ W + bias ----------------
// 64 nodes / block. thread t: node = t&63, quad = t>>6 owns 32 output cols.
// Within a warp all lanes share the same quad -> W shared reads are pure broadcast.
// Vs padded to stride 129 -> node-strided reads are bank-conflict free.
#define GEMM_SMEM ((FF * FF + 64 * 129) * (int)sizeof(float))
__global__ void __launch_bounds__(256) k_gemm(const float* __restrict__ W,
                                              const float* __restrict__ bias,
                                              float* __restrict__ out) {
    extern __shared__ float sh[];
    float* Ws = sh;              // 128*128
    float* Vs = sh + FF * FF;    // 64*129

    int tid = threadIdx.x;
    for (int i = tid; i < FF * FF; i += 256) Ws[i] = W[i];

    int n0 = blockIdx.x * 64;
    for (int l = tid; l < 64 * FF; l += 256) {
        int nl = l >> 7, kk = l & 127;
        int n = n0 + nl;
        Vs[nl * 129 + kk] = (n < NN) ? g_buf0[(size_t)n * FF + kk] : 0.0f;
    }
    __syncthreads();

    int nl   = tid & 63;
    int quad = tid >> 6;
    float4 acc[8];
#pragma unroll
    for (int c = 0; c < 8; c++) acc[c] = make_float4(0.f, 0.f, 0.f, 0.f);

    const float* vp = &Vs[nl * 129];
#pragma unroll 4
    for (int kk = 0; kk < FF; kk++) {
        float vk = vp[kk];
        const float4* wr = (const float4*)&Ws[kk * FF + quad * 32];
#pragma unroll
        for (int c = 0; c < 8; c++) {
            float4 w4 = wr[c];
            acc[c].x += vk * w4.x;
            acc[c].y += vk * w4.y;
            acc[c].z += vk * w4.z;
            acc[c].w += vk * w4.w;
        }
    }

    int n = n0 + nl;
    if (n < NN) {
        const float4* b4 = (const float4*)&bias[quad * 32];
        float4* o4 = (float4*)&out[(size_t)n * FF + quad * 32];
#pragma unroll
        for (int c = 0; c < 8; c++) {
            float4 bb = __ldg(&b4[c]);
            o4[c] = make_float4(acc[c].x + bb.x, acc[c].y + bb.y,
                                acc[c].z + bb.z, acc[c].w + bb.w);
        }
    }
}

extern "C" void kernel_launch(void* const* d_in, const int* in_sizes, int n_in,
                              void* d_out, int out_size) {
    const float* x    = (const float*)d_in[0];
    const void*  ei   = d_in[1];
    const float* W    = (const float*)d_in[2];
    const float* bias = (const float*)d_in[3];
    float* out = (float*)d_out;

    cudaFuncSetAttribute(k_gemm, cudaFuncAttributeMaxDynamicSharedMemorySize, GEMM_SMEM);

    k_detect<<<1, 32>>>((const int*)ei);
    k_zero<<<(NN + 255) / 256, 256>>>();
    k_colsum<<<(NN + ROWS_PER_BLK - 1) / ROWS_PER_BLK, FF>>>(x);
    k_degree<<<(EE + 255) / 256, 256>>>(ei);
    k_scan1<<<(NN + 1023) / 1024, 1024>>>();
    k_scan2<<<1, 32>>>();
    k_scan3<<<(NN + 255) / 256, 256>>>();
    k_scatter<<<(EE + 255) / 256, 256>>>(ei);
    k_center<<<(NN * FF + 255) / 256, 256>>>(x);

    // 50 ping-pong propagate steps; final result lands in g_buf0 (even count)
    for (int it = 0; it < ITERS; it++) {
        k_prop<<<(NN * 32 + 255) / 256, 256>>>(it & 1);
    }

    k_gemm<<<(NN + 63) / 64, 256, GEMM_SMEM>>>(W, bias, out);
}